// round 1
// baseline (speedup 1.0000x reference)
#include <cuda_runtime.h>
#include <cuda_bf16.h>
#include <math.h>

// Problem constants
#define NTOK 1024
#define DMODEL 512
#define HID 2048
#define NEXP 8
#define TOPK 2
#define NPAIR (NTOK*TOPK)   // 2048

// ---------------- scratch (device globals; no allocation) ----------------
__device__ float g_hidden[NPAIR * HID];     // 16 MB  FC1 output (post-GELU)
__device__ float g_y2[NPAIR * DMODEL];      // 4 MB   FC2 output
__device__ int   g_cnt[NEXP];
__device__ int   g_off[NEXP];
__device__ int   g_cur[NEXP];
__device__ int   g_tokexp[NPAIR];           // expert id per (token,k)
__device__ float g_score[NPAIR];            // softmax score per (token,k)
__device__ int   g_pos[NPAIR];              // (token,k) -> sorted pair position
__device__ int   g_pair_token[NPAIR];       // sorted pair position -> token

// ---------------- kernel 0: reset ----------------
__global__ void reset_kernel() {
    int t = threadIdx.x;
    if (t < NEXP) { g_cnt[t] = 0; g_cur[t] = 0; }
}

// ---------------- kernel 1: gate (one warp per token) ----------------
__global__ void gate_kernel(const float* __restrict__ inp,
                            const float* __restrict__ gw,
                            const float* __restrict__ gb) {
    int gwarp = (blockIdx.x * blockDim.x + threadIdx.x) >> 5;
    int lane  = threadIdx.x & 31;
    if (gwarp >= NTOK) return;
    const float* x = inp + (size_t)gwarp * DMODEL;
    float acc[NEXP];
#pragma unroll
    for (int e = 0; e < NEXP; e++) acc[e] = 0.f;
    for (int d = lane; d < DMODEL; d += 32) {
        float xv = x[d];
#pragma unroll
        for (int e = 0; e < NEXP; e++) acc[e] += xv * gw[e * DMODEL + d];
    }
#pragma unroll
    for (int e = 0; e < NEXP; e++)
#pragma unroll
        for (int o = 16; o; o >>= 1) acc[e] += __shfl_xor_sync(~0u, acc[e], o);
    if (lane == 0) {
        float best = -1e30f, best2 = -1e30f; int bi = 0, bi2 = 0;
#pragma unroll
        for (int e = 0; e < NEXP; e++) {
            float v = acc[e] + gb[e];
            if (v > best)       { best2 = best; bi2 = bi; best = v; bi = e; }
            else if (v > best2) { best2 = v; bi2 = e; }
        }
        float d  = best2 - best;          // <= 0
        float ed = expf(d);
        float s1 = ed / (1.f + ed);
        float s0 = 1.f / (1.f + ed);
        g_tokexp[gwarp * 2 + 0] = bi;
        g_tokexp[gwarp * 2 + 1] = bi2;
        g_score[gwarp * 2 + 0] = s0;
        g_score[gwarp * 2 + 1] = s1;
        atomicAdd(&g_cnt[bi], 1);
        atomicAdd(&g_cnt[bi2], 1);
    }
}

// ---------------- kernel 2: scan (tiny) ----------------
__global__ void scan_kernel() {
    int s = 0;
    for (int e = 0; e < NEXP; e++) { g_off[e] = s; s += g_cnt[e]; g_cur[e] = 0; }
}

// ---------------- kernel 3: scatter ----------------
__global__ void scatter_kernel() {
    int i = blockIdx.x * blockDim.x + threadIdx.x;
    if (i >= NPAIR) return;
    int e = g_tokexp[i];
    int p = g_off[e] + atomicAdd(&g_cur[e], 1);
    g_pair_token[p] = i >> 1;   // token id
    g_pos[i] = p;
}

// ---------------- grouped SGEMM:  C[p][n] = sum_k A[row][k] * W[e][n][k] + b ----------------
// A is row-gathered (GATHER: via g_pair_token) or direct (row = p).
template<int BM, int BN, int BK, int TM, int TN, bool DO_GELU, bool GATHER>
__global__ void moe_gemm(const float* __restrict__ Abase,
                         const float* __restrict__ Wbase,
                         const float* __restrict__ bias,
                         float* __restrict__ Cbase,
                         int Kdim, int Ndim) {
    const int e   = blockIdx.z;
    const int cnt = g_cnt[e];
    const int m0  = blockIdx.y * BM;
    if (m0 >= cnt) return;
    const int n0  = blockIdx.x * BN;
    const int off = g_off[e];

    __shared__ float As[BK][BM];
    __shared__ float Bs[BK][BN];
    __shared__ int   rowsrc[BM];

    const int tid = threadIdx.x;            // 256 threads
    for (int m = tid; m < BM; m += blockDim.x) {
        int gm = m0 + m;
        int r = -1;
        if (gm < cnt) r = GATHER ? g_pair_token[off + gm] : (off + gm);
        rowsrc[m] = r;
    }
    __syncthreads();

    float acc[TM][TN];
#pragma unroll
    for (int i = 0; i < TM; i++)
#pragma unroll
        for (int j = 0; j < TN; j++) acc[i][j] = 0.f;

    const int tx = tid % (BN / TN);
    const int ty = tid / (BN / TN);
    const float* Wexp = Wbase + (size_t)e * Ndim * Kdim;

    constexpr int KQ = BK / 4;              // float4 per row of k-tile
    constexpr int A_ITERS = (BM * KQ) / 256;
    constexpr int B_ITERS = (BN * KQ) / 256;
    static_assert((BM * KQ) % 256 == 0 && (BN * KQ) % 256 == 0, "load mapping");

    for (int k0 = 0; k0 < Kdim; k0 += BK) {
#pragma unroll
        for (int i = 0; i < A_ITERS; i++) {
            int f   = tid + i * 256;
            int row = f / KQ;
            int kq  = f % KQ;
            int src = rowsrc[row];
            float4 v = make_float4(0.f, 0.f, 0.f, 0.f);
            if (src >= 0)
                v = *(const float4*)(Abase + (size_t)src * Kdim + k0 + kq * 4);
            As[kq * 4 + 0][row] = v.x;
            As[kq * 4 + 1][row] = v.y;
            As[kq * 4 + 2][row] = v.z;
            As[kq * 4 + 3][row] = v.w;
        }
#pragma unroll
        for (int i = 0; i < B_ITERS; i++) {
            int f   = tid + i * 256;
            int row = f / KQ;
            int kq  = f % KQ;
            float4 v = *(const float4*)(Wexp + (size_t)(n0 + row) * Kdim + k0 + kq * 4);
            Bs[kq * 4 + 0][row] = v.x;
            Bs[kq * 4 + 1][row] = v.y;
            Bs[kq * 4 + 2][row] = v.z;
            Bs[kq * 4 + 3][row] = v.w;
        }
        __syncthreads();

#pragma unroll
        for (int kk = 0; kk < BK; kk++) {
            float a[TM], b[TN];
#pragma unroll
            for (int i = 0; i < TM; i += 4) {
                float4 v = *(const float4*)&As[kk][ty * TM + i];
                a[i] = v.x; a[i + 1] = v.y; a[i + 2] = v.z; a[i + 3] = v.w;
            }
#pragma unroll
            for (int j = 0; j < TN; j += 4) {
                float4 v = *(const float4*)&Bs[kk][tx * TN + j];
                b[j] = v.x; b[j + 1] = v.y; b[j + 2] = v.z; b[j + 3] = v.w;
            }
#pragma unroll
            for (int i = 0; i < TM; i++)
#pragma unroll
                for (int j = 0; j < TN; j++) acc[i][j] += a[i] * b[j];
        }
        __syncthreads();
    }

#pragma unroll
    for (int i = 0; i < TM; i++) {
        int m = m0 + ty * TM + i;
        if (m >= cnt) continue;
        int p = off + m;
#pragma unroll
        for (int j = 0; j < TN; j++) {
            int n = n0 + tx * TN + j;
            float v = acc[i][j] + bias[e * Ndim + n];
            if (DO_GELU) v = 0.5f * v * (1.0f + erff(v * 0.70710678118654752f));
            Cbase[(size_t)p * Ndim + n] = v;
        }
    }
}

// ---------------- kernel 6: combine + LayerNorm (one block per token) ----------------
__global__ void combine_ln(const float* __restrict__ lnw,
                           const float* __restrict__ lnb,
                           float* __restrict__ out) {
    int n = blockIdx.x;
    int t = threadIdx.x;                     // 128 threads
    float s0 = g_score[n * 2 + 0], s1 = g_score[n * 2 + 1];
    const float* r0 = g_y2 + (size_t)g_pos[n * 2 + 0] * DMODEL;
    const float* r1 = g_y2 + (size_t)g_pos[n * 2 + 1] * DMODEL;
    float v[4];
    float sum = 0.f, sumsq = 0.f;
#pragma unroll
    for (int j = 0; j < 4; j++) {
        int d = t + j * 128;
        float x = s0 * r0[d] + s1 * r1[d];
        v[j] = x; sum += x; sumsq += x * x;
    }
    __shared__ float red[64];
#pragma unroll
    for (int o = 16; o; o >>= 1) {
        sum   += __shfl_xor_sync(~0u, sum, o);
        sumsq += __shfl_xor_sync(~0u, sumsq, o);
    }
    int w = t >> 5, l = t & 31;
    if (l == 0) { red[w] = sum; red[32 + w] = sumsq; }
    __syncthreads();
    if (t < 32) {
        float a = (l < 4) ? red[l] : 0.f;
        float b = (l < 4) ? red[32 + l] : 0.f;
#pragma unroll
        for (int o = 2; o; o >>= 1) {
            a += __shfl_xor_sync(~0u, a, o);
            b += __shfl_xor_sync(~0u, b, o);
        }
        if (l == 0) { red[0] = a; red[1] = b; }
    }
    __syncthreads();
    float mean = red[0] * (1.0f / DMODEL);
    float var  = red[1] * (1.0f / DMODEL) - mean * mean;
    float rstd = rsqrtf(var + 1e-5f);
#pragma unroll
    for (int j = 0; j < 4; j++) {
        int d = t + j * 128;
        out[(size_t)n * DMODEL + d] = (v[j] - mean) * rstd * lnw[d] + lnb[d];
    }
}

// ---------------- launch ----------------
extern "C" void kernel_launch(void* const* d_in, const int* in_sizes, int n_in,
                              void* d_out, int out_size) {
    const float* inp    = (const float*)d_in[0];   // (1024, 512)
    const float* gate_w = (const float*)d_in[1];   // (8, 512)
    const float* gate_b = (const float*)d_in[2];   // (8,)
    const float* w1     = (const float*)d_in[3];   // (8, 2048, 512)
    const float* b1     = (const float*)d_in[4];   // (8, 2048)
    const float* w2     = (const float*)d_in[5];   // (8, 512, 2048)
    const float* b2     = (const float*)d_in[6];   // (8, 512)
    const float* ln_w   = (const float*)d_in[7];   // (512,)
    const float* ln_b   = (const float*)d_in[8];   // (512,)
    float* out = (float*)d_out;                    // (1024, 512)

    float* hidden; cudaGetSymbolAddress((void**)&hidden, g_hidden);
    float* y2;     cudaGetSymbolAddress((void**)&y2, g_y2);

    reset_kernel<<<1, 32>>>();
    gate_kernel<<<NTOK / 8, 256>>>(inp, gate_w, gate_b);   // 1 warp / token
    scan_kernel<<<1, 1>>>();
    scatter_kernel<<<NPAIR / 256, 256>>>();

    // FC1: [cnt_e x 512] @ w1[e]^T -> [cnt_e x 2048], bias + exact GELU
    {
        dim3 grid(HID / 64, NPAIR / 128, NEXP);
        moe_gemm<128, 64, 16, 8, 4, true, true><<<grid, 256>>>(
            inp, w1, b1, hidden, DMODEL, HID);
    }
    // FC2: [cnt_e x 2048] @ w2[e]^T -> [cnt_e x 512], bias
    {
        dim3 grid(DMODEL / 64, NPAIR / 64, NEXP);
        moe_gemm<64, 64, 16, 4, 4, false, false><<<grid, 256>>>(
            hidden, w2, b2, y2, HID, DMODEL);
    }
    combine_ln<<<NTOK, 128>>>(ln_w, ln_b, out);
}

// round 2
// speedup vs baseline: 3.5277x; 3.5277x over previous
#include <cuda_runtime.h>
#include <cuda_bf16.h>
#include <math.h>
#include <stdint.h>

// Problem constants
#define NTOK 1024
#define DMODEL 512
#define HID 2048
#define NEXP 8
#define TOPK 2
#define NPAIR (NTOK*TOPK)   // 2048

// ---------------- scratch (device globals; no allocation) ----------------
__device__ float g_hidden[NPAIR * HID];     // 16 MB  FC1 output (post-GELU)
__device__ float g_y2[NPAIR * DMODEL];      // 4 MB   FC2 output
__device__ int   g_cnt[NEXP];
__device__ int   g_off[NEXP];
__device__ int   g_cur[NEXP];
__device__ int   g_tokexp[NPAIR];
__device__ float g_score[NPAIR];
__device__ int   g_pos[NPAIR];
__device__ int   g_pair_token[NPAIR];

// ---------------- kernel 0: reset ----------------
__global__ void reset_kernel() {
    int t = threadIdx.x;
    if (t < NEXP) { g_cnt[t] = 0; g_cur[t] = 0; }
}

// ---------------- kernel 1: gate (one warp per token) ----------------
__global__ void gate_kernel(const float* __restrict__ inp,
                            const float* __restrict__ gw,
                            const float* __restrict__ gb) {
    int gwarp = (blockIdx.x * blockDim.x + threadIdx.x) >> 5;
    int lane  = threadIdx.x & 31;
    if (gwarp >= NTOK) return;
    const float* x = inp + (size_t)gwarp * DMODEL;
    float acc[NEXP];
#pragma unroll
    for (int e = 0; e < NEXP; e++) acc[e] = 0.f;
    for (int d = lane; d < DMODEL; d += 32) {
        float xv = x[d];
#pragma unroll
        for (int e = 0; e < NEXP; e++) acc[e] += xv * gw[e * DMODEL + d];
    }
#pragma unroll
    for (int e = 0; e < NEXP; e++)
#pragma unroll
        for (int o = 16; o; o >>= 1) acc[e] += __shfl_xor_sync(~0u, acc[e], o);
    if (lane == 0) {
        float best = -1e30f, best2 = -1e30f; int bi = 0, bi2 = 0;
#pragma unroll
        for (int e = 0; e < NEXP; e++) {
            float v = acc[e] + gb[e];
            if (v > best)       { best2 = best; bi2 = bi; best = v; bi = e; }
            else if (v > best2) { best2 = v; bi2 = e; }
        }
        float d  = best2 - best;
        float ed = expf(d);
        float s1 = ed / (1.f + ed);
        float s0 = 1.f / (1.f + ed);
        g_tokexp[gwarp * 2 + 0] = bi;
        g_tokexp[gwarp * 2 + 1] = bi2;
        g_score[gwarp * 2 + 0] = s0;
        g_score[gwarp * 2 + 1] = s1;
        atomicAdd(&g_cnt[bi], 1);
        atomicAdd(&g_cnt[bi2], 1);
    }
}

// ---------------- kernel 2: scan ----------------
__global__ void scan_kernel() {
    int s = 0;
    for (int e = 0; e < NEXP; e++) { g_off[e] = s; s += g_cnt[e]; g_cur[e] = 0; }
}

// ---------------- kernel 3: scatter ----------------
__global__ void scatter_kernel() {
    int i = blockIdx.x * blockDim.x + threadIdx.x;
    if (i >= NPAIR) return;
    int e = g_tokexp[i];
    int p = g_off[e] + atomicAdd(&g_cur[e], 1);
    g_pair_token[p] = i >> 1;
    g_pos[i] = p;
}

// ---------------- tensor-core helpers ----------------
__device__ __forceinline__ void ldsm_x4(uint32_t addr, uint32_t* r) {
    asm volatile("ldmatrix.sync.aligned.m8n8.x4.shared.b16 {%0,%1,%2,%3}, [%4];"
                 : "=r"(r[0]), "=r"(r[1]), "=r"(r[2]), "=r"(r[3]) : "r"(addr));
}
__device__ __forceinline__ void mma_bf16(float* d, const uint32_t* a,
                                         uint32_t b0, uint32_t b1) {
    asm volatile("mma.sync.aligned.m16n8k16.row.col.f32.bf16.bf16.f32 "
                 "{%0,%1,%2,%3},{%4,%5,%6,%7},{%8,%9},{%0,%1,%2,%3};"
                 : "+f"(d[0]), "+f"(d[1]), "+f"(d[2]), "+f"(d[3])
                 : "r"(a[0]), "r"(a[1]), "r"(a[2]), "r"(a[3]), "r"(b0), "r"(b1));
}
// split fp32 pair into packed bf16 hi / lo words
__device__ __forceinline__ void cvt2(float x, float y, uint32_t& hi, uint32_t& lo) {
    __nv_bfloat16 hx = __float2bfloat16(x), hy = __float2bfloat16(y);
    float rx = x - __bfloat162float(hx);
    float ry = y - __bfloat162float(hy);
    __nv_bfloat16 lx = __float2bfloat16(rx), ly = __float2bfloat16(ry);
    hi = ((uint32_t)__bfloat16_as_ushort(hy) << 16) | __bfloat16_as_ushort(hx);
    lo = ((uint32_t)__bfloat16_as_ushort(ly) << 16) | __bfloat16_as_ushort(lx);
}

// ---------------- grouped GEMM, bf16 hi/lo split on tensor cores ----------------
// C[p][n] = sum_k A[row][k] * W[e][n][k] + bias[e][n]   (optional exact GELU)
// A rows gathered via g_pair_token (GATHER) or direct (p).
template<int BM, int BN, bool DO_GELU, bool GATHER>
__global__ __launch_bounds__(256, 1)
void moe_gemm_tc(const float* __restrict__ Abase,
                 const float* __restrict__ Wbase,
                 const float* __restrict__ bias,
                 float* __restrict__ Cbase,
                 int Kdim, int Ndim) {
    constexpr int BK = 32;
    constexpr int PK = 40;             // padded row pitch (elems) -> 80 B, ldmatrix conflict-free
    constexpr int WC = 4, WR = 2;
    constexpr int WM = BM / WR, WN = BN / WC;
    constexpr int MT = WM / 16, NT = WN / 8;
    constexpr int A_IT = BM * 8 / 256; // float4 loads per thread for A tile
    constexpr int B_IT = BN * 8 / 256;

    const int e   = blockIdx.z;
    const int cnt = g_cnt[e];
    const int m0  = blockIdx.y * BM;
    if (m0 >= cnt) return;
    const int n0  = blockIdx.x * BN;
    const int off = g_off[e];

    __shared__ __nv_bfloat16 Ah[BM * PK], Al[BM * PK];
    __shared__ __nv_bfloat16 Bh[BN * PK], Bl[BN * PK];
    __shared__ int rowsrc[BM];

    const int tid  = threadIdx.x;
    const int lane = tid & 31;
    const int w    = tid >> 5;
    const int mwarp = (w >> 2) * WM;
    const int nwarp = (w & 3) * WN;

    if (tid < BM) {
        int gm = m0 + tid; int r = -1;
        if (gm < cnt) r = GATHER ? g_pair_token[off + gm] : (off + gm);
        rowsrc[tid] = r;
    }
    __syncthreads();

    const float* Wexp = Wbase + (size_t)e * Ndim * Kdim;

    // per-thread global load pointers
    const float* pA[A_IT];
    const float* pB[B_IT];
#pragma unroll
    for (int i = 0; i < A_IT; i++) {
        int f = tid + i * 256, row = f >> 3, q = f & 7;
        int src = rowsrc[row];
        pA[i] = (src >= 0) ? (Abase + (size_t)src * Kdim + 4 * q) : nullptr;
    }
#pragma unroll
    for (int i = 0; i < B_IT; i++) {
        int f = tid + i * 256, row = f >> 3, q = f & 7;
        pB[i] = Wexp + (size_t)(n0 + row) * Kdim + 4 * q;
    }

    float acc[MT][NT][4];
#pragma unroll
    for (int i = 0; i < MT; i++)
#pragma unroll
        for (int j = 0; j < NT; j++)
#pragma unroll
            for (int c = 0; c < 4; c++) acc[i][j][c] = 0.f;

    float4 aA[A_IT], aB[B_IT];
#pragma unroll
    for (int i = 0; i < A_IT; i++)
        aA[i] = pA[i] ? *(const float4*)(pA[i]) : make_float4(0.f, 0.f, 0.f, 0.f);
#pragma unroll
    for (int i = 0; i < B_IT; i++)
        aB[i] = *(const float4*)(pB[i]);

    const uint32_t sAh = (uint32_t)__cvta_generic_to_shared(Ah);
    const uint32_t sAl = (uint32_t)__cvta_generic_to_shared(Al);
    const uint32_t sBh = (uint32_t)__cvta_generic_to_shared(Bh);
    const uint32_t sBl = (uint32_t)__cvta_generic_to_shared(Bl);

    for (int kc = 0; kc < Kdim; kc += BK) {
        // convert + STS
#pragma unroll
        for (int i = 0; i < A_IT; i++) {
            int f = tid + i * 256, row = f >> 3, q = f & 7;
            uint32_t h0, l0, h1, l1;
            cvt2(aA[i].x, aA[i].y, h0, l0);
            cvt2(aA[i].z, aA[i].w, h1, l1);
            *(uint2*)&Ah[row * PK + q * 4] = make_uint2(h0, h1);
            *(uint2*)&Al[row * PK + q * 4] = make_uint2(l0, l1);
        }
#pragma unroll
        for (int i = 0; i < B_IT; i++) {
            int f = tid + i * 256, row = f >> 3, q = f & 7;
            uint32_t h0, l0, h1, l1;
            cvt2(aB[i].x, aB[i].y, h0, l0);
            cvt2(aB[i].z, aB[i].w, h1, l1);
            *(uint2*)&Bh[row * PK + q * 4] = make_uint2(h0, h1);
            *(uint2*)&Bl[row * PK + q * 4] = make_uint2(l0, l1);
        }
        __syncthreads();

        // prefetch next chunk (overlaps with MMA below)
        if (kc + BK < Kdim) {
#pragma unroll
            for (int i = 0; i < A_IT; i++)
                aA[i] = pA[i] ? *(const float4*)(pA[i] + kc + BK)
                              : make_float4(0.f, 0.f, 0.f, 0.f);
#pragma unroll
            for (int i = 0; i < B_IT; i++)
                aB[i] = *(const float4*)(pB[i] + kc + BK);
        }

        // compute: 2 k16 steps
#pragma unroll
        for (int ks = 0; ks < 2; ks++) {
            uint32_t fa_h[MT][4], fa_l[MT][4];
#pragma unroll
            for (int mt = 0; mt < MT; mt++) {
                int row = mwarp + 16 * mt + (lane & 15);
                int col = 16 * ks + ((lane >> 4) << 3);
                uint32_t o = (uint32_t)(row * PK + col) * 2;
                ldsm_x4(sAh + o, fa_h[mt]);
                ldsm_x4(sAl + o, fa_l[mt]);
            }
            uint32_t fb_h[NT / 2][4], fb_l[NT / 2][4];
#pragma unroll
            for (int np = 0; np < NT / 2; np++) {
                int row = nwarp + 16 * np + ((lane >> 4) << 3) + (lane & 7);
                int col = 16 * ks + (((lane >> 3) & 1) << 3);
                uint32_t o = (uint32_t)(row * PK + col) * 2;
                ldsm_x4(sBh + o, fb_h[np]);
                ldsm_x4(sBl + o, fb_l[np]);
            }
#pragma unroll
            for (int mt = 0; mt < MT; mt++)
#pragma unroll
                for (int nt = 0; nt < NT; nt++) {
                    int np = nt >> 1, half = (nt & 1) << 1;
                    uint32_t bh0 = fb_h[np][half], bh1 = fb_h[np][half + 1];
                    uint32_t bl0 = fb_l[np][half], bl1 = fb_l[np][half + 1];
                    mma_bf16(acc[mt][nt], fa_h[mt], bh0, bh1);
                    mma_bf16(acc[mt][nt], fa_h[mt], bl0, bl1);
                    mma_bf16(acc[mt][nt], fa_l[mt], bh0, bh1);
                }
        }
        __syncthreads();
    }

    // epilogue
    const int g = lane >> 2, tig = lane & 3;
#pragma unroll
    for (int mt = 0; mt < MT; mt++) {
#pragma unroll
        for (int nt = 0; nt < NT; nt++) {
            int col = n0 + nwarp + 8 * nt + 2 * tig;
            float b0 = bias[e * Ndim + col];
            float b1 = bias[e * Ndim + col + 1];
            int r0 = m0 + mwarp + 16 * mt + g;
            int r1 = r0 + 8;
            float v0 = acc[mt][nt][0] + b0;
            float v1 = acc[mt][nt][1] + b1;
            float v2 = acc[mt][nt][2] + b0;
            float v3 = acc[mt][nt][3] + b1;
            if (DO_GELU) {
                v0 = 0.5f * v0 * (1.0f + erff(v0 * 0.70710678118654752f));
                v1 = 0.5f * v1 * (1.0f + erff(v1 * 0.70710678118654752f));
                v2 = 0.5f * v2 * (1.0f + erff(v2 * 0.70710678118654752f));
                v3 = 0.5f * v3 * (1.0f + erff(v3 * 0.70710678118654752f));
            }
            if (r0 < cnt) *(float2*)&Cbase[(size_t)(off + r0) * Ndim + col] = make_float2(v0, v1);
            if (r1 < cnt) *(float2*)&Cbase[(size_t)(off + r1) * Ndim + col] = make_float2(v2, v3);
        }
    }
}

// ---------------- combine + LayerNorm ----------------
__global__ void combine_ln(const float* __restrict__ lnw,
                           const float* __restrict__ lnb,
                           float* __restrict__ out) {
    int n = blockIdx.x;
    int t = threadIdx.x;                     // 128 threads
    float s0 = g_score[n * 2 + 0], s1 = g_score[n * 2 + 1];
    const float* r0 = g_y2 + (size_t)g_pos[n * 2 + 0] * DMODEL;
    const float* r1 = g_y2 + (size_t)g_pos[n * 2 + 1] * DMODEL;
    float v[4];
    float sum = 0.f, sumsq = 0.f;
#pragma unroll
    for (int j = 0; j < 4; j++) {
        int d = t + j * 128;
        float x = s0 * r0[d] + s1 * r1[d];
        v[j] = x; sum += x; sumsq += x * x;
    }
    __shared__ float red[64];
#pragma unroll
    for (int o = 16; o; o >>= 1) {
        sum   += __shfl_xor_sync(~0u, sum, o);
        sumsq += __shfl_xor_sync(~0u, sumsq, o);
    }
    int w = t >> 5, l = t & 31;
    if (l == 0) { red[w] = sum; red[32 + w] = sumsq; }
    __syncthreads();
    if (t < 32) {
        float a = (l < 4) ? red[l] : 0.f;
        float b = (l < 4) ? red[32 + l] : 0.f;
#pragma unroll
        for (int o = 2; o; o >>= 1) {
            a += __shfl_xor_sync(~0u, a, o);
            b += __shfl_xor_sync(~0u, b, o);
        }
        if (l == 0) { red[0] = a; red[1] = b; }
    }
    __syncthreads();
    float mean = red[0] * (1.0f / DMODEL);
    float var  = red[1] * (1.0f / DMODEL) - mean * mean;
    float rstd = rsqrtf(var + 1e-5f);
#pragma unroll
    for (int j = 0; j < 4; j++) {
        int d = t + j * 128;
        out[(size_t)n * DMODEL + d] = (v[j] - mean) * rstd * lnw[d] + lnb[d];
    }
}

// ---------------- launch ----------------
extern "C" void kernel_launch(void* const* d_in, const int* in_sizes, int n_in,
                              void* d_out, int out_size) {
    const float* inp    = (const float*)d_in[0];
    const float* gate_w = (const float*)d_in[1];
    const float* gate_b = (const float*)d_in[2];
    const float* w1     = (const float*)d_in[3];
    const float* b1     = (const float*)d_in[4];
    const float* w2     = (const float*)d_in[5];
    const float* b2     = (const float*)d_in[6];
    const float* ln_w   = (const float*)d_in[7];
    const float* ln_b   = (const float*)d_in[8];
    float* out = (float*)d_out;

    float* hidden; cudaGetSymbolAddress((void**)&hidden, g_hidden);
    float* y2;     cudaGetSymbolAddress((void**)&y2, g_y2);

    reset_kernel<<<1, 32>>>();
    gate_kernel<<<NTOK / 8, 256>>>(inp, gate_w, gate_b);
    scan_kernel<<<1, 1>>>();
    scatter_kernel<<<NPAIR / 256, 256>>>();

    // FC1: [cnt_e x 512] @ w1[e]^T -> [cnt_e x 2048], bias + exact GELU
    {
        dim3 grid(HID / 128, NPAIR / 128, NEXP);
        moe_gemm_tc<128, 128, true, true><<<grid, 256>>>(
            inp, w1, b1, hidden, DMODEL, HID);
    }
    // FC2: [cnt_e x 2048] @ w2[e]^T -> [cnt_e x 512], bias
    {
        dim3 grid(DMODEL / 128, NPAIR / 64, NEXP);
        moe_gemm_tc<64, 128, false, false><<<grid, 256>>>(
            hidden, w2, b2, y2, HID, DMODEL);
    }
    combine_ln<<<NTOK, 128>>>(ln_w, ln_b, out);
}